// round 5
// baseline (speedup 1.0000x reference)
#include <cuda_runtime.h>
#include <cuda_bf16.h>
#include <math.h>
#include <stdint.h>

#define BATCH 8192
#define PIX 784
#define WIRES 10
#define DIM 1024
#define QDEPTH 20
#define NGATES (QDEPTH * WIRES)   // 200

#define KBIG 3072                 // [hi | lo | hi] concatenated K
#define NBIG 1664                 // 832 j-slots x (re,im) interleaved
#define BKT  64                   // K per smem tile
#define NKT  (KBIG / BKT)         // 48

// ---------------- scratch ----------------
__device__ float  g_ca[BATCH * WIRES];
__device__ float  g_sa[BATCH * WIRES];
__device__ float2 g_gates[NGATES * 4];
__device__ float  g_Ure[DIM * DIM];             // [k][j]
__device__ float  g_Uim[DIM * DIM];             // [k][j]
__device__ __nv_bfloat16 g_As[(size_t)BATCH * KBIG];   // A' [m][k]
__device__ __nv_bfloat16 g_Bb[(size_t)NBIG * KBIG];    // B' [n][k]

// ---------------- helpers ----------------
__device__ __forceinline__ uint32_t smem_u32(const void* p) {
    uint32_t a;
    asm("{ .reg .u64 t; cvta.to.shared.u64 t, %1; cvt.u32.u64 %0, t; }" : "=r"(a) : "l"(p));
    return a;
}
__device__ __forceinline__ void cp_async16(uint32_t dst, const void* src) {
    asm volatile("cp.async.cg.shared.global [%0], [%1], 16;" :: "r"(dst), "l"(src));
}
#define CP_COMMIT() asm volatile("cp.async.commit_group;" ::: "memory")
#define CP_WAIT1()  asm volatile("cp.async.wait_group 1;" ::: "memory")

__device__ __forceinline__ void ldsm_x4(uint32_t* r, uint32_t addr) {
    asm volatile("ldmatrix.sync.aligned.m8n8.x4.shared.b16 {%0,%1,%2,%3}, [%4];"
                 : "=r"(r[0]), "=r"(r[1]), "=r"(r[2]), "=r"(r[3]) : "r"(addr));
}
__device__ __forceinline__ void mma16816(float* d, const uint32_t* a, const uint32_t* b) {
    asm volatile(
        "mma.sync.aligned.m16n8k16.row.col.f32.bf16.bf16.f32 "
        "{%0,%1,%2,%3}, {%4,%5,%6,%7}, {%8,%9}, {%0,%1,%2,%3};"
        : "+f"(d[0]), "+f"(d[1]), "+f"(d[2]), "+f"(d[3])
        : "r"(a[0]), "r"(a[1]), "r"(a[2]), "r"(a[3]), "r"(b[0]), "r"(b[1]));
}

// ---------------- kernel 1: angles ----------------
__global__ __launch_bounds__(256) void k_angles(const float* __restrict__ x,
                                                const float* __restrict__ W,
                                                const float* __restrict__ bias) {
    int warp = (blockIdx.x * blockDim.x + threadIdx.x) >> 5;
    int lane = threadIdx.x & 31;
    if (warp >= BATCH) return;
    const float* xr = x + (size_t)warp * PIX;
    float acc[WIRES];
#pragma unroll
    for (int w = 0; w < WIRES; w++) acc[w] = 0.f;
    for (int p = lane; p < PIX; p += 32) {
        float xv = xr[p];
#pragma unroll
        for (int w = 0; w < WIRES; w++)
            acc[w] = fmaf(xv, __ldg(&W[w * PIX + p]), acc[w]);
    }
#pragma unroll
    for (int w = 0; w < WIRES; w++) {
        float v = acc[w];
#pragma unroll
        for (int o = 16; o; o >>= 1) v += __shfl_xor_sync(0xffffffffu, v, o);
        acc[w] = v;
    }
    if (lane == 0) {
#pragma unroll
        for (int w = 0; w < WIRES; w++) {
            float h = 0.5f * (acc[w] + bias[w]);
            g_ca[warp * WIRES + w] = cosf(h);
            g_sa[warp * WIRES + w] = sinf(h);
        }
    }
}

// ---------------- kernel 2: Rot gates ----------------
__global__ void k_gates(const float* __restrict__ qw) {
    int g = blockIdx.x * blockDim.x + threadIdx.x;
    if (g >= NGATES) return;
    float phi = qw[g * 3 + 0], th = qw[g * 3 + 1], om = qw[g * 3 + 2];
    float c = cosf(0.5f * th), s = sinf(0.5f * th);
    float A = 0.5f * (phi + om), B = 0.5f * (phi - om);
    float cA = cosf(A), sA = sinf(A), cB = cosf(B), sB = sinf(B);
    g_gates[g * 4 + 0] = make_float2(cA * c, -sA * c);
    g_gates[g * 4 + 1] = make_float2(-cB * s, -sB * s);
    g_gates[g * 4 + 2] = make_float2(cB * s, -sB * s);
    g_gates[g * 4 + 3] = make_float2(cA * c,  sA * c);
}

// ---------------- kernel 3: build U ----------------
__global__ __launch_bounds__(512) void k_buildU() {
    __shared__ float2 st[DIM];
    __shared__ float2 gs[NGATES * 4];
    const int t = threadIdx.x;
    const int col = blockIdx.x;

    for (int i = t; i < NGATES * 4; i += 512) gs[i] = g_gates[i];
    st[t]       = make_float2(t == col ? 1.f : 0.f, 0.f);
    st[t + 512] = make_float2((t + 512) == col ? 1.f : 0.f, 0.f);
    __syncthreads();

    for (int l = 0; l < QDEPTH; l++) {
        for (int w = 0; w < WIRES; w++) {
            const int gi = (l * WIRES + w) * 4;
            const float2 g00 = gs[gi + 0], g01 = gs[gi + 1];
            const float2 g10 = gs[gi + 2], g11 = gs[gi + 3];
            const int mask = 1 << (9 - w);
            const int low = t & (mask - 1);
            const int i0 = ((t & ~(mask - 1)) << 1) | low;
            const int i1 = i0 | mask;
            const float2 a0 = st[i0], a1 = st[i1];
            float2 n0, n1;
            n0.x = g00.x * a0.x - g00.y * a0.y + g01.x * a1.x - g01.y * a1.y;
            n0.y = g00.x * a0.y + g00.y * a0.x + g01.x * a1.y + g01.y * a1.x;
            n1.x = g10.x * a0.x - g10.y * a0.y + g11.x * a1.x - g11.y * a1.y;
            n1.y = g10.x * a0.y + g10.y * a0.x + g11.x * a1.y + g11.y * a1.x;
            st[i0] = n0; st[i1] = n1;
            __syncthreads();
        }
        const int r = (l % (WIRES - 1)) + 1;
        int p0 = t, p1 = t + 512;
#pragma unroll
        for (int w = WIRES - 1; w >= 0; w--) {
            const int cm = 1 << (9 - w);
            const int tm = 1 << (9 - ((w + r) % WIRES));
            if (p0 & cm) p0 ^= tm;
            if (p1 & cm) p1 ^= tm;
        }
        const float2 v0 = st[p0], v1 = st[p1];
        __syncthreads();
        st[t] = v0; st[t + 512] = v1;
        __syncthreads();
    }
    g_Ure[col * DIM + t]       = st[t].x;
    g_Uim[col * DIM + t]       = st[t].y;
    g_Ure[col * DIM + t + 512] = st[t + 512].x;
    g_Uim[col * DIM + t + 512] = st[t + 512].y;
}

// ---------------- kernel 4: A' = split product state (vectorized stores) --------
__global__ __launch_bounds__(256) void k_A() {
    __shared__ float cL[32], cR[32];
    const int b = blockIdx.x;
    const int t = threadIdx.x;
    if (t < 32) {
        float p = 1.f;
#pragma unroll
        for (int w = 0; w < 5; w++) {
            int bit = (t >> (4 - w)) & 1;
            p *= bit ? g_sa[b * WIRES + w] : g_ca[b * WIRES + w];
        }
        cL[t] = p;
    } else if (t < 64) {
        int l = t - 32;
        float p = 1.f;
#pragma unroll
        for (int w = 0; w < 5; w++) {
            int bit = (l >> (4 - w)) & 1;
            p *= bit ? g_sa[b * WIRES + 5 + w] : g_ca[b * WIRES + 5 + w];
        }
        cR[l] = p;
    }
    __syncthreads();
    __nv_bfloat16* row = g_As + (size_t)b * KBIG;
    const int i0 = t * 4;
    const float l4 = cL[i0 >> 5];
    ushort hi4[4], lo4[4];
#pragma unroll
    for (int q = 0; q < 4; q++) {
        float s = l4 * cR[(i0 & 31) + q];
        __nv_bfloat16 hi = __float2bfloat16(s);
        __nv_bfloat16 lo = __float2bfloat16(s - __bfloat162float(hi));
        hi4[q] = *(ushort*)&hi;
        lo4[q] = *(ushort*)&lo;
    }
    uint2 hv = make_uint2((uint32_t)hi4[0] | ((uint32_t)hi4[1] << 16),
                          (uint32_t)hi4[2] | ((uint32_t)hi4[3] << 16));
    uint2 lv = make_uint2((uint32_t)lo4[0] | ((uint32_t)lo4[1] << 16),
                          (uint32_t)lo4[2] | ((uint32_t)lo4[3] << 16));
    *(uint2*)(row + i0)        = hv;
    *(uint2*)(row + i0 + 1024) = lv;
    *(uint2*)(row + i0 + 2048) = hv;
}

// ---------------- kernel 5: B' = transpose + split U ----------------
__global__ void k_B() {
    __shared__ float sre[32][33], sim[32][33];
    const int k0 = blockIdx.x * 32, j0 = blockIdx.y * 32;
    const int tx = threadIdx.x, ty = threadIdx.y;
    for (int r = ty; r < 32; r += 8) {
        sre[r][tx] = g_Ure[(k0 + r) * DIM + j0 + tx];
        sim[r][tx] = g_Uim[(k0 + r) * DIM + j0 + tx];
    }
    __syncthreads();
    for (int jl = ty; jl < 32; jl += 8) {
        int j = j0 + jl, k = k0 + tx;
        float vr = sre[tx][jl], vi = sim[tx][jl];
        __nv_bfloat16 hr = __float2bfloat16(vr);
        __nv_bfloat16 lr = __float2bfloat16(vr - __bfloat162float(hr));
        __nv_bfloat16 hi = __float2bfloat16(vi);
        __nv_bfloat16 li = __float2bfloat16(vi - __bfloat162float(hi));
        __nv_bfloat16* rR = g_Bb + (size_t)(2 * j) * KBIG;
        __nv_bfloat16* rI = rR + KBIG;
        rR[k] = hr; rR[k + 1024] = hr; rR[k + 2048] = lr;
        rI[k] = hi; rI[k + 1024] = hi; rI[k + 2048] = li;
    }
}

// ---------------- kernel 6: mma.sync bf16 GEMM + epilogue ----------------
// BM=256, BN=128, BK=64, 3-stage cp.async, 256 threads, 8 warps (4 M x 2 N),
// warp tile 64x64, one __syncthreads per K-tile.
#define STAGE_BYTES 49152          // A 32KB + B 16KB
#define GEMM_SMEM   (3 * STAGE_BYTES)   // 147456

__device__ __forceinline__ void load_tile(uint32_t sbase, int stage, int kt,
                                          const __nv_bfloat16* gA,
                                          const __nv_bfloat16* gB, int tid) {
    const uint32_t aS = sbase + stage * STAGE_BYTES;
    const uint32_t bS = aS + 32768;
    const int r0 = tid >> 3;        // 0..31
    const int c  = tid & 7;         // 0..7 (16B chunks)
    const uint32_t cx = (uint32_t)(c * 16);
#pragma unroll
    for (int p = 0; p < 8; p++) {
        const int row = p * 32 + r0;
        const uint32_t off = (uint32_t)(row * 128) + (cx ^ ((row & 7) * 16));
        cp_async16(aS + off, gA + (size_t)row * KBIG + (size_t)kt * BKT + c * 8);
    }
#pragma unroll
    for (int p = 0; p < 4; p++) {
        const int row = p * 32 + r0;
        const uint32_t off = (uint32_t)(row * 128) + (cx ^ ((row & 7) * 16));
        cp_async16(bS + off, gB + (size_t)row * KBIG + (size_t)kt * BKT + c * 8);
    }
}

__global__ __launch_bounds__(256, 1) void k_gemm(float* __restrict__ out) {
    extern __shared__ char smem[];
    const uint32_t sbase = smem_u32(smem);
    const int tid = threadIdx.x;
    const int wid = tid >> 5, lane = tid & 31;
    const int wm = wid >> 1, wn = wid & 1;      // 4 x 2 warp grid
    const int m0 = blockIdx.x * 256;
    const int n0 = blockIdx.y * 128;

    const __nv_bfloat16* gA = g_As + (size_t)m0 * KBIG;
    const __nv_bfloat16* gB = g_Bb + (size_t)n0 * KBIG;

    float acc[4][8][4];
#pragma unroll
    for (int i = 0; i < 4; i++)
#pragma unroll
        for (int j = 0; j < 8; j++)
#pragma unroll
            for (int q = 0; q < 4; q++) acc[i][j][q] = 0.f;

    load_tile(sbase, 0, 0, gA, gB, tid); CP_COMMIT();
    load_tile(sbase, 1, 1, gA, gB, tid); CP_COMMIT();

    // per-lane ldmatrix in-tile row/col offsets
    const int a_row = wm * 64 + (lane & 7) + ((lane >> 3) & 1) * 8;
    const uint32_t a_kx = ((lane >> 4) & 1) * 16;
    const uint32_t a_sw = (uint32_t)((a_row & 7) * 16);
    const int b_row = wn * 64 + (lane & 7) + ((lane >> 4) & 1) * 8;
    const uint32_t b_kx = ((lane >> 3) & 1) * 16;
    const uint32_t b_sw = (uint32_t)((b_row & 7) * 16);

    for (int kt = 0; kt < NKT; kt++) {
        CP_WAIT1();
        __syncthreads();
        if (kt + 2 < NKT) load_tile(sbase, (kt + 2) % 3, kt + 2, gA, gB, tid);
        CP_COMMIT();

        const uint32_t aS = sbase + (kt % 3) * STAGE_BYTES;
        const uint32_t bS = aS + 32768;
#pragma unroll
        for (int ks = 0; ks < 4; ks++) {
            uint32_t afr[4][4], bfr[4][4];
            const uint32_t akb = ((uint32_t)(ks * 32) + a_kx) ^ a_sw;
            const uint32_t bkb = ((uint32_t)(ks * 32) + b_kx) ^ b_sw;
#pragma unroll
            for (int mf = 0; mf < 4; mf++)
                ldsm_x4(afr[mf], aS + (uint32_t)((a_row + mf * 16) * 128) + akb);
#pragma unroll
            for (int nf2 = 0; nf2 < 4; nf2++)
                ldsm_x4(bfr[nf2], bS + (uint32_t)((b_row + nf2 * 16) * 128) + bkb);
#pragma unroll
            for (int mf = 0; mf < 4; mf++)
#pragma unroll
                for (int nf = 0; nf < 8; nf++)
                    mma16816(acc[mf][nf], afr[mf], &bfr[nf >> 1][(nf & 1) * 2]);
        }
    }

    // epilogue: (c0,c1) = (re,im) of pixel j; (c2,c3) = row+8
    const int jbase = (n0 >> 1) + wn * 32;
    const int rbase = m0 + wm * 64 + (lane >> 2);
    const int jq = lane & 3;
#pragma unroll
    for (int mf = 0; mf < 4; mf++) {
#pragma unroll
        for (int nf = 0; nf < 8; nf++) {
            const int j = jbase + nf * 4 + jq;
            if (j < PIX) {
                const float re0 = acc[mf][nf][0], im0 = acc[mf][nf][1];
                const float re1 = acc[mf][nf][2], im1 = acc[mf][nf][3];
                out[(size_t)(rbase + mf * 16) * PIX + j] =
                    fminf((re0 * re0 + im0 * im0) * (float)PIX, 1.0f);
                out[(size_t)(rbase + mf * 16 + 8) * PIX + j] =
                    fminf((re1 * re1 + im1 * im1) * (float)PIX, 1.0f);
            }
        }
    }
}

// ---------------- launch ----------------
extern "C" void kernel_launch(void* const* d_in, const int* in_sizes, int n_in,
                              void* d_out, int out_size) {
    const float* x  = (const float*)d_in[0];
    const float* W  = (const float*)d_in[1];
    const float* b  = (const float*)d_in[2];
    const float* qw = (const float*)d_in[3];
    float* out = (float*)d_out;

    cudaFuncSetAttribute(k_gemm, cudaFuncAttributeMaxDynamicSharedMemorySize, GEMM_SMEM);

    k_angles<<<BATCH / 8, 256>>>(x, W, b);
    k_gates<<<1, 256>>>(qw);
    k_buildU<<<DIM, 512>>>();
    k_A<<<BATCH, 256>>>();
    dim3 gB(32, 26);
    k_B<<<gB, dim3(32, 8)>>>();
    dim3 gg(BATCH / 256, NBIG / 128);   // 32 x 13
    k_gemm<<<gg, 256, GEMM_SMEM>>>(out);
}

// round 7
// speedup vs baseline: 1.2273x; 1.2273x over previous
#include <cuda_runtime.h>
#include <cuda_fp16.h>
#include <math.h>
#include <stdint.h>

#define BATCH 8192
#define PIX 784
#define WIRES 10
#define DIM 1024
#define QDEPTH 20
#define NGATES (QDEPTH * WIRES)   // 200

#define KBIG 2048                 // [Ah | Al] x [Bh | Bh]
#define NBIG 1664                 // 832 j-slots x (re,im) interleaved
#define BKT  64                   // K per smem tile
#define NKT  (KBIG / BKT)         // 32

// ---------------- scratch ----------------
__device__ float  g_ca[BATCH * WIRES];
__device__ float  g_sa[BATCH * WIRES];
__device__ float2 g_gates[NGATES * 4];
__device__ float  g_Ure[DIM * DIM];             // [k][j]
__device__ float  g_Uim[DIM * DIM];             // [k][j]
__device__ __half g_As[(size_t)BATCH * KBIG];   // A' [m][k]
__device__ __half g_Bb[(size_t)NBIG * KBIG];    // B' [n][k]

// ---------------- helpers ----------------
__device__ __forceinline__ uint32_t smem_u32(const void* p) {
    uint32_t a;
    asm("{ .reg .u64 t; cvta.to.shared.u64 t, %1; cvt.u32.u64 %0, t; }" : "=r"(a) : "l"(p));
    return a;
}
__device__ __forceinline__ void cp_async16(uint32_t dst, const void* src) {
    asm volatile("cp.async.cg.shared.global [%0], [%1], 16;" :: "r"(dst), "l"(src));
}
#define CP_COMMIT() asm volatile("cp.async.commit_group;" ::: "memory")
#define CP_WAIT2()  asm volatile("cp.async.wait_group 2;" ::: "memory")

__device__ __forceinline__ void ldsm_x4(uint32_t* r, uint32_t addr) {
    asm volatile("ldmatrix.sync.aligned.m8n8.x4.shared.b16 {%0,%1,%2,%3}, [%4];"
                 : "=r"(r[0]), "=r"(r[1]), "=r"(r[2]), "=r"(r[3]) : "r"(addr));
}
__device__ __forceinline__ void mma16816(float* d, const uint32_t* a, const uint32_t* b) {
    asm volatile(
        "mma.sync.aligned.m16n8k16.row.col.f32.f16.f16.f32 "
        "{%0,%1,%2,%3}, {%4,%5,%6,%7}, {%8,%9}, {%0,%1,%2,%3};"
        : "+f"(d[0]), "+f"(d[1]), "+f"(d[2]), "+f"(d[3])
        : "r"(a[0]), "r"(a[1]), "r"(a[2]), "r"(a[3]), "r"(b[0]), "r"(b[1]));
}

// ---------------- kernel 1: angles ----------------
__global__ __launch_bounds__(256) void k_angles(const float* __restrict__ x,
                                                const float* __restrict__ W,
                                                const float* __restrict__ bias) {
    int warp = (blockIdx.x * blockDim.x + threadIdx.x) >> 5;
    int lane = threadIdx.x & 31;
    if (warp >= BATCH) return;
    const float* xr = x + (size_t)warp * PIX;
    float acc[WIRES];
#pragma unroll
    for (int w = 0; w < WIRES; w++) acc[w] = 0.f;
    for (int p = lane; p < PIX; p += 32) {
        float xv = xr[p];
#pragma unroll
        for (int w = 0; w < WIRES; w++)
            acc[w] = fmaf(xv, __ldg(&W[w * PIX + p]), acc[w]);
    }
#pragma unroll
    for (int w = 0; w < WIRES; w++) {
        float v = acc[w];
#pragma unroll
        for (int o = 16; o; o >>= 1) v += __shfl_xor_sync(0xffffffffu, v, o);
        acc[w] = v;
    }
    if (lane == 0) {
#pragma unroll
        for (int w = 0; w < WIRES; w++) {
            float h = 0.5f * (acc[w] + bias[w]);
            g_ca[warp * WIRES + w] = cosf(h);
            g_sa[warp * WIRES + w] = sinf(h);
        }
    }
}

// ---------------- kernel 2: Rot gates ----------------
__global__ void k_gates(const float* __restrict__ qw) {
    int g = blockIdx.x * blockDim.x + threadIdx.x;
    if (g >= NGATES) return;
    float phi = qw[g * 3 + 0], th = qw[g * 3 + 1], om = qw[g * 3 + 2];
    float c = cosf(0.5f * th), s = sinf(0.5f * th);
    float A = 0.5f * (phi + om), B = 0.5f * (phi - om);
    float cA = cosf(A), sA = sinf(A), cB = cosf(B), sB = sinf(B);
    g_gates[g * 4 + 0] = make_float2(cA * c, -sA * c);
    g_gates[g * 4 + 1] = make_float2(-cB * s, -sB * s);
    g_gates[g * 4 + 2] = make_float2(cB * s, -sB * s);
    g_gates[g * 4 + 3] = make_float2(cA * c,  sA * c);
}

// ---------------- kernel 3: build U ----------------
__global__ __launch_bounds__(512) void k_buildU() {
    __shared__ float2 st[DIM];
    __shared__ float2 gs[NGATES * 4];
    const int t = threadIdx.x;
    const int col = blockIdx.x;

    for (int i = t; i < NGATES * 4; i += 512) gs[i] = g_gates[i];
    st[t]       = make_float2(t == col ? 1.f : 0.f, 0.f);
    st[t + 512] = make_float2((t + 512) == col ? 1.f : 0.f, 0.f);
    __syncthreads();

    for (int l = 0; l < QDEPTH; l++) {
        for (int w = 0; w < WIRES; w++) {
            const int gi = (l * WIRES + w) * 4;
            const float2 g00 = gs[gi + 0], g01 = gs[gi + 1];
            const float2 g10 = gs[gi + 2], g11 = gs[gi + 3];
            const int mask = 1 << (9 - w);
            const int low = t & (mask - 1);
            const int i0 = ((t & ~(mask - 1)) << 1) | low;
            const int i1 = i0 | mask;
            const float2 a0 = st[i0], a1 = st[i1];
            float2 n0, n1;
            n0.x = g00.x * a0.x - g00.y * a0.y + g01.x * a1.x - g01.y * a1.y;
            n0.y = g00.x * a0.y + g00.y * a0.x + g01.x * a1.y + g01.y * a1.x;
            n1.x = g10.x * a0.x - g10.y * a0.y + g11.x * a1.x - g11.y * a1.y;
            n1.y = g10.x * a0.y + g10.y * a0.x + g11.x * a1.y + g11.y * a1.x;
            st[i0] = n0; st[i1] = n1;
            __syncthreads();
        }
        const int r = (l % (WIRES - 1)) + 1;
        int p0 = t, p1 = t + 512;
#pragma unroll
        for (int w = WIRES - 1; w >= 0; w--) {
            const int cm = 1 << (9 - w);
            const int tm = 1 << (9 - ((w + r) % WIRES));
            if (p0 & cm) p0 ^= tm;
            if (p1 & cm) p1 ^= tm;
        }
        const float2 v0 = st[p0], v1 = st[p1];
        __syncthreads();
        st[t] = v0; st[t + 512] = v1;
        __syncthreads();
    }
    g_Ure[col * DIM + t]       = st[t].x;
    g_Uim[col * DIM + t]       = st[t].y;
    g_Ure[col * DIM + t + 512] = st[t + 512].x;
    g_Uim[col * DIM + t + 512] = st[t + 512].y;
}

// ---------------- kernel 4: A' = [hi | lo] fp16 split of product state ----------
__global__ __launch_bounds__(256) void k_A() {
    __shared__ float cL[32], cR[32];
    const int b = blockIdx.x;
    const int t = threadIdx.x;
    if (t < 32) {
        float p = 1.f;
#pragma unroll
        for (int w = 0; w < 5; w++) {
            int bit = (t >> (4 - w)) & 1;
            p *= bit ? g_sa[b * WIRES + w] : g_ca[b * WIRES + w];
        }
        cL[t] = p;
    } else if (t < 64) {
        int l = t - 32;
        float p = 1.f;
#pragma unroll
        for (int w = 0; w < 5; w++) {
            int bit = (l >> (4 - w)) & 1;
            p *= bit ? g_sa[b * WIRES + 5 + w] : g_ca[b * WIRES + 5 + w];
        }
        cR[l] = p;
    }
    __syncthreads();
    __half* row = g_As + (size_t)b * KBIG;
    const int i0 = t * 4;
    const float l4 = cL[i0 >> 5];
    ushort hi4[4], lo4[4];
#pragma unroll
    for (int q = 0; q < 4; q++) {
        float s = l4 * cR[(i0 & 31) + q];
        __half hi = __float2half_rn(s);
        __half lo = __float2half_rn(s - __half2float(hi));
        hi4[q] = *(ushort*)&hi;
        lo4[q] = *(ushort*)&lo;
    }
    uint2 hv = make_uint2((uint32_t)hi4[0] | ((uint32_t)hi4[1] << 16),
                          (uint32_t)hi4[2] | ((uint32_t)hi4[3] << 16));
    uint2 lv = make_uint2((uint32_t)lo4[0] | ((uint32_t)lo4[1] << 16),
                          (uint32_t)lo4[2] | ((uint32_t)lo4[3] << 16));
    *(uint2*)(row + i0)        = hv;
    *(uint2*)(row + i0 + 1024) = lv;
}

// ---------------- kernel 5: B' = transpose + fp16 U, hi duplicated --------------
__global__ void k_B() {
    __shared__ float sre[32][33], sim[32][33];
    const int k0 = blockIdx.x * 32, j0 = blockIdx.y * 32;
    const int tx = threadIdx.x, ty = threadIdx.y;
    for (int r = ty; r < 32; r += 8) {
        sre[r][tx] = g_Ure[(k0 + r) * DIM + j0 + tx];
        sim[r][tx] = g_Uim[(k0 + r) * DIM + j0 + tx];
    }
    __syncthreads();
    for (int jl = ty; jl < 32; jl += 8) {
        int j = j0 + jl, k = k0 + tx;
        __half hr = __float2half_rn(sre[tx][jl]);
        __half hi = __float2half_rn(sim[tx][jl]);
        __half* rR = g_Bb + (size_t)(2 * j) * KBIG;
        __half* rI = rR + KBIG;
        rR[k] = hr; rR[k + 1024] = hr;
        rI[k] = hi; rI[k + 1024] = hi;
    }
}

// ---------------- kernel 6: mma.sync fp16 GEMM + epilogue ----------------
// BM=128, BN=128, BK=64, 3-stage cp.async, 8 warps (2 M x 4 N), warp tile 64x32.
#define STAGE_BYTES 32768
#define GEMM_SMEM   (3 * STAGE_BYTES)   // 98304

__device__ __forceinline__ void load_tile(uint32_t sbase, int stage, int kt,
                                          const __half* gA,
                                          const __half* gB, int tid) {
    const uint32_t aS = sbase + stage * STAGE_BYTES;
    const uint32_t bS = aS + 16384;
    const int r0 = tid >> 3;        // 0..31
    const int c  = tid & 7;         // 0..7 (16B chunks)
    const uint32_t cx = (uint32_t)(c * 16);
#pragma unroll
    for (int p = 0; p < 4; p++) {
        const int row = p * 32 + r0;
        const uint32_t off = (uint32_t)(row * 128) + (cx ^ ((row & 7) * 16));
        cp_async16(aS + off, gA + (size_t)row * KBIG + (size_t)kt * BKT + c * 8);
    }
#pragma unroll
    for (int p = 0; p < 4; p++) {
        const int row = p * 32 + r0;
        const uint32_t off = (uint32_t)(row * 128) + (cx ^ ((row & 7) * 16));
        cp_async16(bS + off, gB + (size_t)row * KBIG + (size_t)kt * BKT + c * 8);
    }
}

__global__ __launch_bounds__(256, 2) void k_gemm(float* __restrict__ out) {
    extern __shared__ char smem[];
    const uint32_t sbase = smem_u32(smem);
    const int tid = threadIdx.x;
    const int wid = tid >> 5, lane = tid & 31;
    const int wm = wid & 1, wn = wid >> 1;      // 2 x 4 warp grid
    const int m0 = blockIdx.x * 128;
    const int n0 = blockIdx.y * 128;

    const __half* gA = g_As + (size_t)m0 * KBIG;
    const __half* gB = g_Bb + (size_t)n0 * KBIG;

    float acc[4][4][4];
#pragma unroll
    for (int i = 0; i < 4; i++)
#pragma unroll
        for (int j = 0; j < 4; j++)
#pragma unroll
            for (int q = 0; q < 4; q++) acc[i][j][q] = 0.f;

    load_tile(sbase, 0, 0, gA, gB, tid); CP_COMMIT();
    load_tile(sbase, 1, 1, gA, gB, tid); CP_COMMIT();

    const int a_row = wm * 64 + (lane & 7) + ((lane >> 3) & 1) * 8;
    const uint32_t a_kx = ((lane >> 4) & 1) * 16;
    const int b_row = wn * 32 + (lane & 7) + ((lane >> 4) & 1) * 8;
    const uint32_t b_kx = ((lane >> 3) & 1) * 16;

    int stage = 0;
    for (int kt = 0; kt < NKT; kt++) {
        if (kt + 2 < NKT) load_tile(sbase, (stage + 2) % 3, kt + 2, gA, gB, tid);
        CP_COMMIT();
        CP_WAIT2();
        __syncthreads();

        const uint32_t aS = sbase + stage * STAGE_BYTES;
        const uint32_t bS = aS + 16384;
#pragma unroll
        for (int ks = 0; ks < 4; ks++) {
            uint32_t afr[4][4], bfr[2][4];
#pragma unroll
            for (int mf = 0; mf < 4; mf++) {
                const int row = a_row + mf * 16;
                const uint32_t kb = (uint32_t)(ks * 32) + a_kx;
                ldsm_x4(afr[mf], aS + (uint32_t)(row * 128) + (kb ^ ((row & 7) * 16)));
            }
#pragma unroll
            for (int nf2 = 0; nf2 < 2; nf2++) {
                const int row = b_row + nf2 * 16;
                const uint32_t kb = (uint32_t)(ks * 32) + b_kx;
                ldsm_x4(bfr[nf2], bS + (uint32_t)(row * 128) + (kb ^ ((row & 7) * 16)));
            }
#pragma unroll
            for (int mf = 0; mf < 4; mf++)
#pragma unroll
                for (int nf = 0; nf < 4; nf++)
                    mma16816(acc[mf][nf], afr[mf], &bfr[nf >> 1][(nf & 1) * 2]);
        }
        __syncthreads();
        stage = (stage + 1) % 3;
    }

    // epilogue: (c0,c1) = (re,im) of pixel j; (c2,c3) = row+8
    const int jbase = (n0 >> 1) + wn * 16;
    const int rbase = m0 + wm * 64 + (lane >> 2);
    const int jq = lane & 3;
#pragma unroll
    for (int mf = 0; mf < 4; mf++) {
#pragma unroll
        for (int nf = 0; nf < 4; nf++) {
            const int j = jbase + nf * 4 + jq;
            if (j < PIX) {
                const float re0 = acc[mf][nf][0], im0 = acc[mf][nf][1];
                const float re1 = acc[mf][nf][2], im1 = acc[mf][nf][3];
                out[(size_t)(rbase + mf * 16) * PIX + j] =
                    fminf((re0 * re0 + im0 * im0) * (float)PIX, 1.0f);
                out[(size_t)(rbase + mf * 16 + 8) * PIX + j] =
                    fminf((re1 * re1 + im1 * im1) * (float)PIX, 1.0f);
            }
        }
    }
}

// ---------------- launch ----------------
extern "C" void kernel_launch(void* const* d_in, const int* in_sizes, int n_in,
                              void* d_out, int out_size) {
    const float* x  = (const float*)d_in[0];
    const float* W  = (const float*)d_in[1];
    const float* b  = (const float*)d_in[2];
    const float* qw = (const float*)d_in[3];
    float* out = (float*)d_out;

    cudaFuncSetAttribute(k_gemm, cudaFuncAttributeMaxDynamicSharedMemorySize, GEMM_SMEM);

    k_angles<<<BATCH / 8, 256>>>(x, W, b);
    k_gates<<<1, 256>>>(qw);
    k_buildU<<<DIM, 512>>>();
    k_A<<<BATCH, 256>>>();
    dim3 gB(32, 26);
    k_B<<<gB, dim3(32, 8)>>>();
    dim3 gg(BATCH / 128, NBIG / 128);   // 64 x 13
    k_gemm<<<gg, 256, GEMM_SMEM>>>(out);
}

// round 8
// speedup vs baseline: 1.5066x; 1.2276x over previous
#include <cuda_runtime.h>
#include <cuda_fp16.h>
#include <math.h>
#include <stdint.h>

#define BATCH 8192
#define PIX 784
#define WIRES 10
#define DIM 1024
#define QDEPTH 20
#define NGATES (QDEPTH * WIRES)   // 200

#define KBIG 1024                 // pure fp16: A=fp16(S), B=fp16(U)
#define NBIG 1664                 // 832 j-slots x (re,im) interleaved
#define BKT  64                   // K per smem tile
#define NKT  (KBIG / BKT)         // 16

// ---------------- scratch ----------------
__device__ float  g_ca[BATCH * WIRES];
__device__ float  g_sa[BATCH * WIRES];
__device__ float2 g_gates[NGATES * 4];
__device__ float  g_Ure[DIM * DIM];             // [k][j]
__device__ float  g_Uim[DIM * DIM];             // [k][j]
__device__ __half g_As[(size_t)BATCH * KBIG];   // A' [m][k]
__device__ __half g_Bb[(size_t)NBIG * KBIG];    // B' [n][k]

// ---------------- helpers ----------------
__device__ __forceinline__ uint32_t smem_u32(const void* p) {
    uint32_t a;
    asm("{ .reg .u64 t; cvta.to.shared.u64 t, %1; cvt.u32.u64 %0, t; }" : "=r"(a) : "l"(p));
    return a;
}
__device__ __forceinline__ void cp_async16(uint32_t dst, const void* src) {
    asm volatile("cp.async.cg.shared.global [%0], [%1], 16;" :: "r"(dst), "l"(src));
}
#define CP_COMMIT() asm volatile("cp.async.commit_group;" ::: "memory")
#define CP_WAIT2()  asm volatile("cp.async.wait_group 2;" ::: "memory")

__device__ __forceinline__ void ldsm_x4(uint32_t* r, uint32_t addr) {
    asm volatile("ldmatrix.sync.aligned.m8n8.x4.shared.b16 {%0,%1,%2,%3}, [%4];"
                 : "=r"(r[0]), "=r"(r[1]), "=r"(r[2]), "=r"(r[3]) : "r"(addr));
}
__device__ __forceinline__ void mma16816(float* d, const uint32_t* a, const uint32_t* b) {
    asm volatile(
        "mma.sync.aligned.m16n8k16.row.col.f32.f16.f16.f32 "
        "{%0,%1,%2,%3}, {%4,%5,%6,%7}, {%8,%9}, {%0,%1,%2,%3};"
        : "+f"(d[0]), "+f"(d[1]), "+f"(d[2]), "+f"(d[3])
        : "r"(a[0]), "r"(a[1]), "r"(a[2]), "r"(a[3]), "r"(b[0]), "r"(b[1]));
}

// ---------------- kernel 1: angles ----------------
__global__ __launch_bounds__(256) void k_angles(const float* __restrict__ x,
                                                const float* __restrict__ W,
                                                const float* __restrict__ bias) {
    int warp = (blockIdx.x * blockDim.x + threadIdx.x) >> 5;
    int lane = threadIdx.x & 31;
    if (warp >= BATCH) return;
    const float* xr = x + (size_t)warp * PIX;
    float acc[WIRES];
#pragma unroll
    for (int w = 0; w < WIRES; w++) acc[w] = 0.f;
    for (int p = lane; p < PIX; p += 32) {
        float xv = xr[p];
#pragma unroll
        for (int w = 0; w < WIRES; w++)
            acc[w] = fmaf(xv, __ldg(&W[w * PIX + p]), acc[w]);
    }
#pragma unroll
    for (int w = 0; w < WIRES; w++) {
        float v = acc[w];
#pragma unroll
        for (int o = 16; o; o >>= 1) v += __shfl_xor_sync(0xffffffffu, v, o);
        acc[w] = v;
    }
    if (lane == 0) {
#pragma unroll
        for (int w = 0; w < WIRES; w++) {
            float h = 0.5f * (acc[w] + bias[w]);
            g_ca[warp * WIRES + w] = cosf(h);
            g_sa[warp * WIRES + w] = sinf(h);
        }
    }
}

// ---------------- kernel 2: Rot gates ----------------
__global__ void k_gates(const float* __restrict__ qw) {
    int g = blockIdx.x * blockDim.x + threadIdx.x;
    if (g >= NGATES) return;
    float phi = qw[g * 3 + 0], th = qw[g * 3 + 1], om = qw[g * 3 + 2];
    float c = cosf(0.5f * th), s = sinf(0.5f * th);
    float A = 0.5f * (phi + om), B = 0.5f * (phi - om);
    float cA = cosf(A), sA = sinf(A), cB = cosf(B), sB = sinf(B);
    g_gates[g * 4 + 0] = make_float2(cA * c, -sA * c);
    g_gates[g * 4 + 1] = make_float2(-cB * s, -sB * s);
    g_gates[g * 4 + 2] = make_float2(cB * s, -sB * s);
    g_gates[g * 4 + 3] = make_float2(cA * c,  sA * c);
}

// ---------------- kernel 3: build U ----------------
__global__ __launch_bounds__(512) void k_buildU() {
    __shared__ float2 st[DIM];
    __shared__ float2 gs[NGATES * 4];
    const int t = threadIdx.x;
    const int col = blockIdx.x;

    for (int i = t; i < NGATES * 4; i += 512) gs[i] = g_gates[i];
    st[t]       = make_float2(t == col ? 1.f : 0.f, 0.f);
    st[t + 512] = make_float2((t + 512) == col ? 1.f : 0.f, 0.f);
    __syncthreads();

    for (int l = 0; l < QDEPTH; l++) {
        for (int w = 0; w < WIRES; w++) {
            const int gi = (l * WIRES + w) * 4;
            const float2 g00 = gs[gi + 0], g01 = gs[gi + 1];
            const float2 g10 = gs[gi + 2], g11 = gs[gi + 3];
            const int mask = 1 << (9 - w);
            const int low = t & (mask - 1);
            const int i0 = ((t & ~(mask - 1)) << 1) | low;
            const int i1 = i0 | mask;
            const float2 a0 = st[i0], a1 = st[i1];
            float2 n0, n1;
            n0.x = g00.x * a0.x - g00.y * a0.y + g01.x * a1.x - g01.y * a1.y;
            n0.y = g00.x * a0.y + g00.y * a0.x + g01.x * a1.y + g01.y * a1.x;
            n1.x = g10.x * a0.x - g10.y * a0.y + g11.x * a1.x - g11.y * a1.y;
            n1.y = g10.x * a0.y + g10.y * a0.x + g11.x * a1.y + g11.y * a1.x;
            st[i0] = n0; st[i1] = n1;
            __syncthreads();
        }
        const int r = (l % (WIRES - 1)) + 1;
        int p0 = t, p1 = t + 512;
#pragma unroll
        for (int w = WIRES - 1; w >= 0; w--) {
            const int cm = 1 << (9 - w);
            const int tm = 1 << (9 - ((w + r) % WIRES));
            if (p0 & cm) p0 ^= tm;
            if (p1 & cm) p1 ^= tm;
        }
        const float2 v0 = st[p0], v1 = st[p1];
        __syncthreads();
        st[t] = v0; st[t + 512] = v1;
        __syncthreads();
    }
    g_Ure[col * DIM + t]       = st[t].x;
    g_Uim[col * DIM + t]       = st[t].y;
    g_Ure[col * DIM + t + 512] = st[t + 512].x;
    g_Uim[col * DIM + t + 512] = st[t + 512].y;
}

// ---------------- kernel 4: A' = fp16 product state ----------
__global__ __launch_bounds__(256) void k_A() {
    __shared__ float cL[32], cR[32];
    const int b = blockIdx.x;
    const int t = threadIdx.x;
    if (t < 32) {
        float p = 1.f;
#pragma unroll
        for (int w = 0; w < 5; w++) {
            int bit = (t >> (4 - w)) & 1;
            p *= bit ? g_sa[b * WIRES + w] : g_ca[b * WIRES + w];
        }
        cL[t] = p;
    } else if (t < 64) {
        int l = t - 32;
        float p = 1.f;
#pragma unroll
        for (int w = 0; w < 5; w++) {
            int bit = (l >> (4 - w)) & 1;
            p *= bit ? g_sa[b * WIRES + 5 + w] : g_ca[b * WIRES + 5 + w];
        }
        cR[l] = p;
    }
    __syncthreads();
    __half* row = g_As + (size_t)b * KBIG;
    const int i0 = t * 4;
    const float l4 = cL[i0 >> 5];
    ushort hi4[4];
#pragma unroll
    for (int q = 0; q < 4; q++) {
        __half hi = __float2half_rn(l4 * cR[(i0 & 31) + q]);
        hi4[q] = *(ushort*)&hi;
    }
    uint2 hv = make_uint2((uint32_t)hi4[0] | ((uint32_t)hi4[1] << 16),
                          (uint32_t)hi4[2] | ((uint32_t)hi4[3] << 16));
    *(uint2*)(row + i0) = hv;
}

// ---------------- kernel 5: B' = transpose + fp16 U ----------------
__global__ void k_B() {
    __shared__ float sre[32][33], sim[32][33];
    const int k0 = blockIdx.x * 32, j0 = blockIdx.y * 32;
    const int tx = threadIdx.x, ty = threadIdx.y;
    for (int r = ty; r < 32; r += 8) {
        sre[r][tx] = g_Ure[(k0 + r) * DIM + j0 + tx];
        sim[r][tx] = g_Uim[(k0 + r) * DIM + j0 + tx];
    }
    __syncthreads();
    for (int jl = ty; jl < 32; jl += 8) {
        int j = j0 + jl, k = k0 + tx;
        __half hr = __float2half_rn(sre[tx][jl]);
        __half hi = __float2half_rn(sim[tx][jl]);
        g_Bb[(size_t)(2 * j) * KBIG + k]     = hr;
        g_Bb[(size_t)(2 * j + 1) * KBIG + k] = hi;
    }
}

// ---------------- kernel 6: mma.sync fp16 GEMM + epilogue ----------------
// BM=128, BN=128, BK=64, 3-stage cp.async, 8 warps (2 M x 4 N), warp tile 64x32.
#define STAGE_BYTES 32768
#define GEMM_SMEM   (3 * STAGE_BYTES)   // 98304

__device__ __forceinline__ void load_tile(uint32_t sbase, int stage, int kt,
                                          const __half* gA,
                                          const __half* gB, int tid) {
    const uint32_t aS = sbase + stage * STAGE_BYTES;
    const uint32_t bS = aS + 16384;
    const int r0 = tid >> 3;        // 0..31
    const int c  = tid & 7;         // 0..7 (16B chunks)
    const uint32_t cx = (uint32_t)(c * 16);
#pragma unroll
    for (int p = 0; p < 4; p++) {
        const int row = p * 32 + r0;
        const uint32_t off = (uint32_t)(row * 128) + (cx ^ ((row & 7) * 16));
        cp_async16(aS + off, gA + (size_t)row * KBIG + (size_t)kt * BKT + c * 8);
    }
#pragma unroll
    for (int p = 0; p < 4; p++) {
        const int row = p * 32 + r0;
        const uint32_t off = (uint32_t)(row * 128) + (cx ^ ((row & 7) * 16));
        cp_async16(bS + off, gB + (size_t)row * KBIG + (size_t)kt * BKT + c * 8);
    }
}

__global__ __launch_bounds__(256, 2) void k_gemm(float* __restrict__ out) {
    extern __shared__ char smem[];
    const uint32_t sbase = smem_u32(smem);
    const int tid = threadIdx.x;
    const int wid = tid >> 5, lane = tid & 31;
    const int wm = wid & 1, wn = wid >> 1;      // 2 x 4 warp grid
    const int m0 = blockIdx.x * 128;
    const int n0 = blockIdx.y * 128;

    const __half* gA = g_As + (size_t)m0 * KBIG;
    const __half* gB = g_Bb + (size_t)n0 * KBIG;

    float acc[4][4][4];
#pragma unroll
    for (int i = 0; i < 4; i++)
#pragma unroll
        for (int j = 0; j < 4; j++)
#pragma unroll
            for (int q = 0; q < 4; q++) acc[i][j][q] = 0.f;

    load_tile(sbase, 0, 0, gA, gB, tid); CP_COMMIT();
    load_tile(sbase, 1, 1, gA, gB, tid); CP_COMMIT();

    const int a_row = wm * 64 + (lane & 7) + ((lane >> 3) & 1) * 8;
    const uint32_t a_kx = ((lane >> 4) & 1) * 16;
    const int b_row = wn * 32 + (lane & 7) + ((lane >> 4) & 1) * 8;
    const uint32_t b_kx = ((lane >> 3) & 1) * 16;

    int stage = 0;
    for (int kt = 0; kt < NKT; kt++) {
        if (kt + 2 < NKT) load_tile(sbase, (stage + 2) % 3, kt + 2, gA, gB, tid);
        CP_COMMIT();
        CP_WAIT2();
        __syncthreads();

        const uint32_t aS = sbase + stage * STAGE_BYTES;
        const uint32_t bS = aS + 16384;
#pragma unroll
        for (int ks = 0; ks < 4; ks++) {
            uint32_t afr[4][4], bfr[2][4];
#pragma unroll
            for (int mf = 0; mf < 4; mf++) {
                const int row = a_row + mf * 16;
                const uint32_t kb = (uint32_t)(ks * 32) + a_kx;
                ldsm_x4(afr[mf], aS + (uint32_t)(row * 128) + (kb ^ ((row & 7) * 16)));
            }
#pragma unroll
            for (int nf2 = 0; nf2 < 2; nf2++) {
                const int row = b_row + nf2 * 16;
                const uint32_t kb = (uint32_t)(ks * 32) + b_kx;
                ldsm_x4(bfr[nf2], bS + (uint32_t)(row * 128) + (kb ^ ((row & 7) * 16)));
            }
#pragma unroll
            for (int mf = 0; mf < 4; mf++)
#pragma unroll
                for (int nf = 0; nf < 4; nf++)
                    mma16816(acc[mf][nf], afr[mf], &bfr[nf >> 1][(nf & 1) * 2]);
        }
        __syncthreads();
        stage = (stage + 1) % 3;
    }

    // epilogue: (c0,c1) = (re,im) of pixel j; (c2,c3) = row+8
    const int jbase = (n0 >> 1) + wn * 16;
    const int rbase = m0 + wm * 64 + (lane >> 2);
    const int jq = lane & 3;
#pragma unroll
    for (int mf = 0; mf < 4; mf++) {
#pragma unroll
        for (int nf = 0; nf < 4; nf++) {
            const int j = jbase + nf * 4 + jq;
            if (j < PIX) {
                const float re0 = acc[mf][nf][0], im0 = acc[mf][nf][1];
                const float re1 = acc[mf][nf][2], im1 = acc[mf][nf][3];
                out[(size_t)(rbase + mf * 16) * PIX + j] =
                    fminf((re0 * re0 + im0 * im0) * (float)PIX, 1.0f);
                out[(size_t)(rbase + mf * 16 + 8) * PIX + j] =
                    fminf((re1 * re1 + im1 * im1) * (float)PIX, 1.0f);
            }
        }
    }
}

// ---------------- launch ----------------
extern "C" void kernel_launch(void* const* d_in, const int* in_sizes, int n_in,
                              void* d_out, int out_size) {
    const float* x  = (const float*)d_in[0];
    const float* W  = (const float*)d_in[1];
    const float* b  = (const float*)d_in[2];
    const float* qw = (const float*)d_in[3];
    float* out = (float*)d_out;

    cudaFuncSetAttribute(k_gemm, cudaFuncAttributeMaxDynamicSharedMemorySize, GEMM_SMEM);

    k_angles<<<BATCH / 8, 256>>>(x, W, b);
    k_gates<<<1, 256>>>(qw);
    k_buildU<<<DIM, 512>>>();
    k_A<<<BATCH, 256>>>();
    dim3 gB(32, 26);
    k_B<<<gB, dim3(32, 8)>>>();
    dim3 gg(BATCH / 128, NBIG / 128);   // 64 x 13
    k_gemm<<<gg, 256, GEMM_SMEM>>>(out);
}

// round 9
// speedup vs baseline: 1.6335x; 1.0843x over previous
#include <cuda_runtime.h>
#include <cuda_fp16.h>
#include <math.h>
#include <stdint.h>

#define BATCH 8192
#define PIX 784
#define WIRES 10
#define DIM 1024
#define QDEPTH 20
#define NGATES (QDEPTH * WIRES)   // 200

#define KBIG 1024                 // pure fp16: A=fp16(S), B=fp16(U)
#define NBIG 1664                 // 832 j-slots x (re,im) interleaved
#define BKT  64                   // K per smem tile
#define NKT  (KBIG / BKT)         // 16

// ---------------- scratch ----------------
__device__ float2 g_gates[NGATES * 4];
__device__ float  g_Ure[DIM * DIM];             // [k][j]
__device__ float  g_Uim[DIM * DIM];             // [k][j]
__device__ __half g_As[(size_t)BATCH * KBIG];   // A' [m][k]
__device__ __half g_Bb[(size_t)NBIG * KBIG];    // B' [n][k]

// ---------------- helpers ----------------
__device__ __forceinline__ uint32_t smem_u32(const void* p) {
    uint32_t a;
    asm("{ .reg .u64 t; cvta.to.shared.u64 t, %1; cvt.u32.u64 %0, t; }" : "=r"(a) : "l"(p));
    return a;
}
__device__ __forceinline__ void cp_async16(uint32_t dst, const void* src) {
    asm volatile("cp.async.cg.shared.global [%0], [%1], 16;" :: "r"(dst), "l"(src));
}
#define CP_COMMIT() asm volatile("cp.async.commit_group;" ::: "memory")
#define CP_WAIT2()  asm volatile("cp.async.wait_group 2;" ::: "memory")

__device__ __forceinline__ void ldsm_x4(uint32_t* r, uint32_t addr) {
    asm volatile("ldmatrix.sync.aligned.m8n8.x4.shared.b16 {%0,%1,%2,%3}, [%4];"
                 : "=r"(r[0]), "=r"(r[1]), "=r"(r[2]), "=r"(r[3]) : "r"(addr));
}
__device__ __forceinline__ void mma16816(float* d, const uint32_t* a, const uint32_t* b) {
    asm volatile(
        "mma.sync.aligned.m16n8k16.row.col.f32.f16.f16.f32 "
        "{%0,%1,%2,%3}, {%4,%5,%6,%7}, {%8,%9}, {%0,%1,%2,%3};"
        : "+f"(d[0]), "+f"(d[1]), "+f"(d[2]), "+f"(d[3])
        : "r"(a[0]), "r"(a[1]), "r"(a[2]), "r"(a[3]), "r"(b[0]), "r"(b[1]));
}
__device__ __forceinline__ float2 cmul(float2 g, float2 v) {
    return make_float2(g.x * v.x - g.y * v.y, g.x * v.y + g.y * v.x);
}
__device__ __forceinline__ float2 cadd(float2 a, float2 b) {
    return make_float2(a.x + b.x, a.y + b.y);
}

// ---------------- kernel 1: fused angles + fp16 product state ----------------
// one warp per batch row; writes g_As[row][0..1024) directly
__global__ __launch_bounds__(256) void k_angA(const float* __restrict__ x,
                                              const float* __restrict__ W,
                                              const float* __restrict__ bias) {
    const int warp = blockIdx.x * 8 + (threadIdx.x >> 5);
    const int lane = threadIdx.x & 31;
    const float* xr = x + (size_t)warp * PIX;
    float acc[WIRES];
#pragma unroll
    for (int w = 0; w < WIRES; w++) acc[w] = 0.f;
    for (int p = lane; p < PIX; p += 32) {
        float xv = xr[p];
#pragma unroll
        for (int w = 0; w < WIRES; w++)
            acc[w] = fmaf(xv, __ldg(&W[w * PIX + p]), acc[w]);
    }
#pragma unroll
    for (int w = 0; w < WIRES; w++) {
#pragma unroll
        for (int o = 16; o; o >>= 1)
            acc[w] += __shfl_xor_sync(0xffffffffu, acc[w], o);
    }
    // lane l: cl = prod over wires 0..4 using bits of l; cr = wires 5..9
    float cl = 1.f, cr = 1.f;
#pragma unroll
    for (int w = 0; w < 5; w++) {
        float h = 0.5f * (acc[w] + __ldg(&bias[w]));
        float s, c; sincosf(h, &s, &c);
        cl *= ((lane >> (4 - w)) & 1) ? s : c;
    }
#pragma unroll
    for (int w = 5; w < 10; w++) {
        float h = 0.5f * (acc[w] + __ldg(&bias[w]));
        float s, c; sincosf(h, &s, &c);
        cr *= ((lane >> (9 - w)) & 1) ? s : c;
    }
    // lane l writes S[l*32 + q] = cl * cR[q], q = 0..31 (64B contiguous)
    char* rowb = (char*)(g_As + (size_t)warp * KBIG) + lane * 64;
#pragma unroll
    for (int q = 0; q < 32; q += 8) {
        uint32_t u[4];
#pragma unroll
        for (int j = 0; j < 4; j++) {
            float r0 = __shfl_sync(0xffffffffu, cr, q + 2 * j);
            float r1 = __shfl_sync(0xffffffffu, cr, q + 2 * j + 1);
            __half2 h2 = __floats2half2_rn(cl * r0, cl * r1);
            u[j] = *(uint32_t*)&h2;
        }
        *(uint4*)(rowb + q * 2) = make_uint4(u[0], u[1], u[2], u[3]);
    }
}

// ---------------- kernel 2: Rot gates ----------------
__global__ void k_gates(const float* __restrict__ qw) {
    int g = blockIdx.x * blockDim.x + threadIdx.x;
    if (g >= NGATES) return;
    float phi = qw[g * 3 + 0], th = qw[g * 3 + 1], om = qw[g * 3 + 2];
    float c = cosf(0.5f * th), s = sinf(0.5f * th);
    float A = 0.5f * (phi + om), B = 0.5f * (phi - om);
    float cA = cosf(A), sA = sinf(A), cB = cosf(B), sB = sinf(B);
    g_gates[g * 4 + 0] = make_float2(cA * c, -sA * c);
    g_gates[g * 4 + 1] = make_float2(-cB * s, -sB * s);
    g_gates[g * 4 + 2] = make_float2(cB * s, -sB * s);
    g_gates[g * 4 + 3] = make_float2(cA * c,  sA * c);
}

// ---------------- kernel 3: build U, register-resident state -----------------
// thread t owns amplitudes {t, t+512} (bit 9 local). Wires by index-bit b=9-w:
//   b=9: local; b in [5,8]: smem exchange (1 barrier, double-buffered);
//   b in [0,4]: intra-warp shfl. CNOT layer: 1 write + 1 barrier + reg gather.
__global__ __launch_bounds__(512) void k_buildU() {
    __shared__ float4 buf[2][512];
    __shared__ float2 gs[NGATES * 4];
    const int t = threadIdx.x;
    const int lane = t & 31;
    const int col = blockIdx.x;

    for (int i = t; i < NGATES * 4; i += 512) gs[i] = g_gates[i];
    float2 a0 = make_float2(t == col ? 1.f : 0.f, 0.f);
    float2 a1 = make_float2((t + 512) == col ? 1.f : 0.f, 0.f);
    __syncthreads();

    int pb = 0;
    for (int l = 0; l < QDEPTH; l++) {
        // wire 0 (bit 9): thread-local pair
        {
            const int gi = (l * WIRES + 0) * 4;
            const float2 g00 = gs[gi], g01 = gs[gi + 1], g10 = gs[gi + 2], g11 = gs[gi + 3];
            float2 n0 = cadd(cmul(g00, a0), cmul(g01, a1));
            float2 n1 = cadd(cmul(g10, a0), cmul(g11, a1));
            a0 = n0; a1 = n1;
        }
        // wires 1..4 (bits 8..5): smem exchange
#pragma unroll
        for (int w = 1; w <= 4; w++) {
            const int gi = (l * WIRES + w) * 4;
            const float2 g00 = gs[gi], g01 = gs[gi + 1], g10 = gs[gi + 2], g11 = gs[gi + 3];
            const int b = 9 - w;
            const int d = 1 << b;
            buf[pb][t] = make_float4(a0.x, a0.y, a1.x, a1.y);
            __syncthreads();
            float4 p4 = buf[pb][t ^ d];
            pb ^= 1;
            float2 p0 = make_float2(p4.x, p4.y), p1 = make_float2(p4.z, p4.w);
            if ((t >> b) & 1) {
                a0 = cadd(cmul(g10, p0), cmul(g11, a0));
                a1 = cadd(cmul(g10, p1), cmul(g11, a1));
            } else {
                a0 = cadd(cmul(g00, a0), cmul(g01, p0));
                a1 = cadd(cmul(g00, a1), cmul(g01, p1));
            }
        }
        // wires 5..9 (bits 4..0): shfl
#pragma unroll
        for (int w = 5; w <= 9; w++) {
            const int gi = (l * WIRES + w) * 4;
            const float2 g00 = gs[gi], g01 = gs[gi + 1], g10 = gs[gi + 2], g11 = gs[gi + 3];
            const int b = 9 - w;
            const int d = 1 << b;
            float2 p0, p1;
            p0.x = __shfl_xor_sync(0xffffffffu, a0.x, d);
            p0.y = __shfl_xor_sync(0xffffffffu, a0.y, d);
            p1.x = __shfl_xor_sync(0xffffffffu, a1.x, d);
            p1.y = __shfl_xor_sync(0xffffffffu, a1.y, d);
            if ((lane >> b) & 1) {
                a0 = cadd(cmul(g10, p0), cmul(g11, a0));
                a1 = cadd(cmul(g10, p1), cmul(g11, a1));
            } else {
                a0 = cadd(cmul(g00, a0), cmul(g01, p0));
                a1 = cadd(cmul(g00, a1), cmul(g01, p1));
            }
        }
        // CNOT ring: composed permutation gather
        const int r = (l % (WIRES - 1)) + 1;
        buf[pb][t] = make_float4(a0.x, a0.y, a1.x, a1.y);
        __syncthreads();
        int p0i = t, p1i = t + 512;
#pragma unroll
        for (int w = WIRES - 1; w >= 0; w--) {
            const int cm = 1 << (9 - w);
            const int tm = 1 << (9 - ((w + r) % WIRES));
            if (p0i & cm) p0i ^= tm;
            if (p1i & cm) p1i ^= tm;
        }
        float4 q0 = buf[pb][p0i & 511];
        a0 = (p0i < 512) ? make_float2(q0.x, q0.y) : make_float2(q0.z, q0.w);
        float4 q1 = buf[pb][p1i & 511];
        a1 = (p1i < 512) ? make_float2(q1.x, q1.y) : make_float2(q1.z, q1.w);
        pb ^= 1;
    }
    g_Ure[col * DIM + t]       = a0.x;
    g_Uim[col * DIM + t]       = a0.y;
    g_Ure[col * DIM + t + 512] = a1.x;
    g_Uim[col * DIM + t + 512] = a1.y;
}

// ---------------- kernel 4: B' = transpose + fp16 U ----------------
__global__ void k_B() {
    __shared__ float sre[32][33], sim[32][33];
    const int k0 = blockIdx.x * 32, j0 = blockIdx.y * 32;
    const int tx = threadIdx.x, ty = threadIdx.y;
    for (int r = ty; r < 32; r += 8) {
        sre[r][tx] = g_Ure[(k0 + r) * DIM + j0 + tx];
        sim[r][tx] = g_Uim[(k0 + r) * DIM + j0 + tx];
    }
    __syncthreads();
    for (int jl = ty; jl < 32; jl += 8) {
        int j = j0 + jl, k = k0 + tx;
        __half hr = __float2half_rn(sre[tx][jl]);
        __half hi = __float2half_rn(sim[tx][jl]);
        g_Bb[(size_t)(2 * j) * KBIG + k]     = hr;
        g_Bb[(size_t)(2 * j + 1) * KBIG + k] = hi;
    }
}

// ---------------- kernel 5: mma.sync fp16 GEMM + epilogue ----------------
// BM=128, BN=128, BK=64, 3-stage cp.async, 8 warps (2 M x 4 N), warp tile 64x32.
#define STAGE_BYTES 32768
#define GEMM_SMEM   (3 * STAGE_BYTES)   // 98304

__device__ __forceinline__ void load_tile(uint32_t sbase, int stage, int kt,
                                          const __half* gA,
                                          const __half* gB, int tid) {
    const uint32_t aS = sbase + stage * STAGE_BYTES;
    const uint32_t bS = aS + 16384;
    const int r0 = tid >> 3;
    const int c  = tid & 7;
    const uint32_t cx = (uint32_t)(c * 16);
#pragma unroll
    for (int p = 0; p < 4; p++) {
        const int row = p * 32 + r0;
        const uint32_t off = (uint32_t)(row * 128) + (cx ^ ((row & 7) * 16));
        cp_async16(aS + off, gA + (size_t)row * KBIG + (size_t)kt * BKT + c * 8);
    }
#pragma unroll
    for (int p = 0; p < 4; p++) {
        const int row = p * 32 + r0;
        const uint32_t off = (uint32_t)(row * 128) + (cx ^ ((row & 7) * 16));
        cp_async16(bS + off, gB + (size_t)row * KBIG + (size_t)kt * BKT + c * 8);
    }
}

__global__ __launch_bounds__(256, 2) void k_gemm(float* __restrict__ out) {
    extern __shared__ char smem[];
    const uint32_t sbase = smem_u32(smem);
    const int tid = threadIdx.x;
    const int wid = tid >> 5, lane = tid & 31;
    const int wm = wid & 1, wn = wid >> 1;      // 2 x 4 warp grid
    const int m0 = blockIdx.x * 128;
    const int n0 = blockIdx.y * 128;

    const __half* gA = g_As + (size_t)m0 * KBIG;
    const __half* gB = g_Bb + (size_t)n0 * KBIG;

    float acc[4][4][4];
#pragma unroll
    for (int i = 0; i < 4; i++)
#pragma unroll
        for (int j = 0; j < 4; j++)
#pragma unroll
            for (int q = 0; q < 4; q++) acc[i][j][q] = 0.f;

    load_tile(sbase, 0, 0, gA, gB, tid); CP_COMMIT();
    load_tile(sbase, 1, 1, gA, gB, tid); CP_COMMIT();

    const int a_row = wm * 64 + (lane & 7) + ((lane >> 3) & 1) * 8;
    const uint32_t a_kx = ((lane >> 4) & 1) * 16;
    const int b_row = wn * 32 + (lane & 7) + ((lane >> 4) & 1) * 8;
    const uint32_t b_kx = ((lane >> 3) & 1) * 16;

    int stage = 0;
    for (int kt = 0; kt < NKT; kt++) {
        if (kt + 2 < NKT) load_tile(sbase, (stage + 2) % 3, kt + 2, gA, gB, tid);
        CP_COMMIT();
        CP_WAIT2();
        __syncthreads();

        const uint32_t aS = sbase + stage * STAGE_BYTES;
        const uint32_t bS = aS + 16384;
#pragma unroll
        for (int ks = 0; ks < 4; ks++) {
            uint32_t afr[4][4], bfr[2][4];
#pragma unroll
            for (int mf = 0; mf < 4; mf++) {
                const int row = a_row + mf * 16;
                const uint32_t kb = (uint32_t)(ks * 32) + a_kx;
                ldsm_x4(afr[mf], aS + (uint32_t)(row * 128) + (kb ^ ((row & 7) * 16)));
            }
#pragma unroll
            for (int nf2 = 0; nf2 < 2; nf2++) {
                const int row = b_row + nf2 * 16;
                const uint32_t kb = (uint32_t)(ks * 32) + b_kx;
                ldsm_x4(bfr[nf2], bS + (uint32_t)(row * 128) + (kb ^ ((row & 7) * 16)));
            }
#pragma unroll
            for (int mf = 0; mf < 4; mf++)
#pragma unroll
                for (int nf = 0; nf < 4; nf++)
                    mma16816(acc[mf][nf], afr[mf], &bfr[nf >> 1][(nf & 1) * 2]);
        }
        __syncthreads();
        stage = (stage + 1) % 3;
    }

    // epilogue: (c0,c1) = (re,im) of pixel j; (c2,c3) = row+8
    const int jbase = (n0 >> 1) + wn * 16;
    const int rbase = m0 + wm * 64 + (lane >> 2);
    const int jq = lane & 3;
#pragma unroll
    for (int mf = 0; mf < 4; mf++) {
#pragma unroll
        for (int nf = 0; nf < 4; nf++) {
            const int j = jbase + nf * 4 + jq;
            if (j < PIX) {
                const float re0 = acc[mf][nf][0], im0 = acc[mf][nf][1];
                const float re1 = acc[mf][nf][2], im1 = acc[mf][nf][3];
                out[(size_t)(rbase + mf * 16) * PIX + j] =
                    fminf((re0 * re0 + im0 * im0) * (float)PIX, 1.0f);
                out[(size_t)(rbase + mf * 16 + 8) * PIX + j] =
                    fminf((re1 * re1 + im1 * im1) * (float)PIX, 1.0f);
            }
        }
    }
}

// ---------------- launch ----------------
extern "C" void kernel_launch(void* const* d_in, const int* in_sizes, int n_in,
                              void* d_out, int out_size) {
    const float* x  = (const float*)d_in[0];
    const float* W  = (const float*)d_in[1];
    const float* b  = (const float*)d_in[2];
    const float* qw = (const float*)d_in[3];
    float* out = (float*)d_out;

    cudaFuncSetAttribute(k_gemm, cudaFuncAttributeMaxDynamicSharedMemorySize, GEMM_SMEM);

    k_gates<<<1, 256>>>(qw);
    k_angA<<<BATCH / 8, 256>>>(x, W, b);
    k_buildU<<<DIM, 512>>>();
    dim3 gB(32, 26);
    k_B<<<gB, dim3(32, 8)>>>();
    dim3 gg(BATCH / 128, NBIG / 128);   // 64 x 13
    k_gemm<<<gg, 256, GEMM_SMEM>>>(out);
}